// round 1
// baseline (speedup 1.0000x reference)
#include <cuda_runtime.h>
#include <cstdint>

#define N_NODES 100000
#define N_EDGES 1600000
#define N_GRAPHS 2048
#define D 128
#define DFC 256
#define DOUT 8

// ---------------- scratch (static device globals; no allocation) ----------------
__device__ float g_agg[(size_t)N_NODES * D];
__device__ float g_hA[(size_t)N_NODES * D];
__device__ float g_hB[(size_t)N_NODES * D];
__device__ float g_pool[(size_t)N_GRAPHS * D];
__device__ float g_cnt[N_GRAPHS];
__device__ float g_fc1[(size_t)N_GRAPHS * DFC];
__device__ int   g_src[N_EDGES];
__device__ int   g_dst[N_EDGES];
__device__ int   g_batch[N_NODES];
__device__ int   g_is64;

// selector: 0 -> external x, 1 -> g_hA, 2 -> g_hB
__device__ __forceinline__ const float* pick_in(const float* x, int sel) {
    return sel == 0 ? x : (sel == 1 ? g_hA : g_hB);
}
__device__ __forceinline__ float* pick_out(int sel) {
    return sel == 1 ? g_hA : g_hB;
}

// ---------------- index dtype detection + conversion ----------------
__global__ void detect_kernel(const void* ei) {
    if (threadIdx.x == 0 && blockIdx.x == 0) {
        const long long* p64 = (const long long*)ei;
        int ok = 1;
        #pragma unroll
        for (int i = 0; i < 16; i++) {
            long long v = p64[i];
            if (v < 0 || v >= N_NODES) ok = 0;
        }
        g_is64 = ok;
    }
}

__global__ void convert_idx_kernel(const void* ei, const void* batch) {
    int i = blockIdx.x * blockDim.x + threadIdx.x;
    int is64 = g_is64;
    if (i < N_EDGES) {
        if (is64) {
            const long long* p = (const long long*)ei;
            g_src[i] = (int)p[i];
            g_dst[i] = (int)p[(size_t)N_EDGES + i];
        } else {
            const int* p = (const int*)ei;
            g_src[i] = p[i];
            g_dst[i] = p[N_EDGES + i];
        }
    }
    if (i < N_NODES) {
        if (is64) g_batch[i] = (int)((const long long*)batch)[i];
        else      g_batch[i] = ((const int*)batch)[i];
    }
}

// ---------------- zero ----------------
__global__ void zero_kernel(float4* p, int n4) {
    int i = blockIdx.x * blockDim.x + threadIdx.x;
    if (i < n4) p[i] = make_float4(0.f, 0.f, 0.f, 0.f);
}

// ---------------- scatter: agg[dst] += h[src], warp per edge ----------------
__global__ void scatter_kernel(const float* __restrict__ x, int sel_in) {
    long long idx = (long long)blockIdx.x * blockDim.x + threadIdx.x;
    int e = (int)(idx >> 5);
    if (e >= N_EDGES) return;
    int lane = (int)(idx & 31);
    const float* h = pick_in(x, sel_in);
    int s = g_src[e];
    int d = g_dst[e];
    const float4* xr = reinterpret_cast<const float4*>(h) + (size_t)s * (D / 4);
    float4* ar = reinterpret_cast<float4*>(g_agg) + (size_t)d * (D / 4);
    float4 v = __ldg(&xr[lane]);
    atomicAdd(&ar[lane], v);
}

// ---------------- fused dual-GEMM + bias + relu ----------------
// out = relu(agg @ Wrel + hin @ Wroot + b), all [*,128]x[128,128]
// block: 256 threads, tile M=128, N=128; thread micro-tile 8 rows x 4 col-pairs.
__global__ __launch_bounds__(256) void gemm_fused_kernel(
    const float* __restrict__ x, int sel_in, int sel_out,
    const float* __restrict__ Wrel, const float* __restrict__ Wroot,
    const float* __restrict__ bias)
{
    __shared__ float As[128][16];
    __shared__ float Bs[16][128];

    const float* hin = pick_in(x, sel_in);
    float* hout = pick_out(sel_out);

    int m0 = blockIdx.x * 128;
    int tid = threadIdx.x;
    int tx = tid & 15;        // col-pair group base
    int ty = tid >> 4;        // row group (0..15), rows ty*8..ty*8+7

    unsigned long long acc[8][4];
    #pragma unroll
    for (int r = 0; r < 8; r++)
        #pragma unroll
        for (int j = 0; j < 4; j++) acc[r][j] = 0ULL;

    #pragma unroll
    for (int phase = 0; phase < 2; phase++) {
        const float* A = phase ? hin : g_agg;
        const float* W = phase ? Wroot : Wrel;
        for (int k0 = 0; k0 < 128; k0 += 16) {
            // load A tile: 128 rows x 16 k = 512 float4, 2 per thread
            #pragma unroll
            for (int i = 0; i < 2; i++) {
                int f = tid * 2 + i;        // 0..511
                int row = f >> 2;
                int c4 = f & 3;
                int gr = m0 + row;
                float4 v = make_float4(0.f, 0.f, 0.f, 0.f);
                if (gr < N_NODES)
                    v = *reinterpret_cast<const float4*>(A + (size_t)gr * 128 + k0 + c4 * 4);
                *reinterpret_cast<float4*>(&As[row][c4 * 4]) = v;
            }
            // load W tile: 16 k x 128 = 512 float4
            #pragma unroll
            for (int i = 0; i < 2; i++) {
                int f = tid * 2 + i;
                int kr = f >> 5;
                int c4 = f & 31;
                float4 v = *reinterpret_cast<const float4*>(W + (size_t)(k0 + kr) * 128 + c4 * 4);
                *reinterpret_cast<float4*>(&Bs[kr][c4 * 4]) = v;
            }
            __syncthreads();

            #pragma unroll
            for (int k = 0; k < 16; k += 4) {
                float4 av[8];
                #pragma unroll
                for (int r = 0; r < 8; r++)
                    av[r] = *reinterpret_cast<const float4*>(&As[ty * 8 + r][k]);
                #pragma unroll
                for (int kk = 0; kk < 4; kk++) {
                    unsigned long long bb[4];
                    const unsigned long long* Brow =
                        reinterpret_cast<const unsigned long long*>(&Bs[k + kk][0]);
                    #pragma unroll
                    for (int j = 0; j < 4; j++) bb[j] = Brow[tx + 16 * j];
                    #pragma unroll
                    for (int r = 0; r < 8; r++) {
                        float a = (kk == 0) ? av[r].x : (kk == 1) ? av[r].y
                                : (kk == 2) ? av[r].z : av[r].w;
                        unsigned long long aa;
                        asm("mov.b64 %0,{%1,%2};" : "=l"(aa) : "f"(a), "f"(a));
                        #pragma unroll
                        for (int j = 0; j < 4; j++)
                            asm("fma.rn.f32x2 %0, %1, %2, %0;"
                                : "+l"(acc[r][j]) : "l"(aa), "l"(bb[j]));
                    }
                }
            }
            __syncthreads();
        }
    }

    // epilogue: bias + relu + store (float2 per col-pair)
    #pragma unroll
    for (int r = 0; r < 8; r++) {
        int gr = m0 + ty * 8 + r;
        if (gr >= N_NODES) break;
        #pragma unroll
        for (int j = 0; j < 4; j++) {
            int p = tx + 16 * j;
            float2 v = *reinterpret_cast<float2*>(&acc[r][j]);
            float lo = fmaxf(v.x + bias[2 * p], 0.f);
            float hi = fmaxf(v.y + bias[2 * p + 1], 0.f);
            *reinterpret_cast<float2*>(&hout[(size_t)gr * 128 + 2 * p]) = make_float2(lo, hi);
        }
    }
}

// ---------------- pooling: sums + counts (warp per node) ----------------
__global__ void pool_kernel(const float* __restrict__ x, int sel_in) {
    long long idx = (long long)blockIdx.x * blockDim.x + threadIdx.x;
    int node = (int)(idx >> 5);
    if (node >= N_NODES) return;
    int lane = (int)(idx & 31);
    const float* h = pick_in(x, sel_in);
    int g = g_batch[node];
    const float4* hr = reinterpret_cast<const float4*>(h) + (size_t)node * (D / 4);
    float4* pr = reinterpret_cast<float4*>(g_pool) + (size_t)g * (D / 4);
    atomicAdd(&pr[lane], __ldg(&hr[lane]));
    if (lane == 0) atomicAdd(&g_cnt[g], 1.0f);
}

__global__ void div_kernel() {
    int i = blockIdx.x * blockDim.x + threadIdx.x;
    if (i >= N_GRAPHS * D) return;
    int g = i >> 7;
    g_pool[i] = g_pool[i] / fmaxf(g_cnt[g], 1.0f);
}

// ---------------- fc1: [G,128] @ [128,256] + b ----------------
__global__ __launch_bounds__(256) void fc1_kernel(
    const float* __restrict__ w, const float* __restrict__ b)
{
    __shared__ float sh[128];
    int g = blockIdx.x;
    int t = threadIdx.x;
    if (t < 128) sh[t] = g_pool[(size_t)g * 128 + t];
    __syncthreads();
    float acc = b[t];
    #pragma unroll 8
    for (int k = 0; k < 128; k++) acc = fmaf(sh[k], w[(size_t)k * 256 + t], acc);
    g_fc1[(size_t)g * 256 + t] = acc;
}

// ---------------- fc2: [G,256] @ [256,8] + b -> output ----------------
__global__ void fc2_kernel(const float* __restrict__ w, const float* __restrict__ b,
                           float* __restrict__ out)
{
    int idx = blockIdx.x * blockDim.x + threadIdx.x;
    if (idx >= N_GRAPHS * DOUT) return;
    int g = idx >> 3, o = idx & 7;
    float acc = b[o];
    #pragma unroll 8
    for (int k = 0; k < 256; k++) acc = fmaf(g_fc1[(size_t)g * 256 + k], w[k * 8 + o], acc);
    out[idx] = acc;
}

// ---------------- launch ----------------
extern "C" void kernel_launch(void* const* d_in, const int* in_sizes, int n_in,
                              void* d_out, int out_size)
{
    const float* x = (const float*)d_in[0];
    const void* ei = d_in[1];
    const void* batch = d_in[2];
    const float* Wrel[4]  = {(const float*)d_in[3], (const float*)d_in[6],
                             (const float*)d_in[9], (const float*)d_in[12]};
    const float* Wroot[4] = {(const float*)d_in[4], (const float*)d_in[7],
                             (const float*)d_in[10], (const float*)d_in[13]};
    const float* bias[4]  = {(const float*)d_in[5], (const float*)d_in[8],
                             (const float*)d_in[11], (const float*)d_in[14]};
    const float* fcw = (const float*)d_in[15];
    const float* fcb = (const float*)d_in[16];
    const float* regw = (const float*)d_in[17];
    const float* regb = (const float*)d_in[18];
    float* out = (float*)d_out;

    // index prep
    detect_kernel<<<1, 32>>>(ei);
    convert_idx_kernel<<<(N_EDGES + 255) / 256, 256>>>(ei, batch);

    const int nAgg4 = N_NODES * D / 4;                      // 3.2M float4
    const int zeroBlocks = (nAgg4 + 255) / 256;
    const int scatterBlocks = (int)(((long long)N_EDGES * 32 + 255) / 256);
    const int gemmBlocks = (N_NODES + 127) / 128;

    // layer chain: in sel: 0=x, 1=hA, 2=hB
    int ins[4]  = {0, 1, 2, 1};
    int outs[4] = {1, 2, 1, 2};
    for (int L = 0; L < 4; L++) {
        zero_kernel<<<zeroBlocks, 256>>>((float4*)nullptr, 0);  // placeholder? no — see below
    }
    // NOTE: zero_kernel needs a target; use dedicated wrappers below instead.
    // (The loop above is a no-op: n4 = 0. Real zeroing happens via zero_agg_kernel.)

    for (int L = 0; L < 4; L++) {
        // zero agg via generic kernel over g_agg (device-global target)
        extern __global__ void zero_agg_kernel();
        zero_agg_kernel<<<zeroBlocks, 256>>>();
        scatter_kernel<<<scatterBlocks, 256>>>(x, ins[L]);
        gemm_fused_kernel<<<gemmBlocks, 256>>>(x, ins[L], outs[L], Wrel[L], Wroot[L], bias[L]);
    }

    // pooling
    extern __global__ void zero_pool_kernel();
    zero_pool_kernel<<<(N_GRAPHS * D / 4 + N_GRAPHS / 4 + 255) / 256, 256>>>();
    pool_kernel<<<(int)(((long long)N_NODES * 32 + 255) / 256), 256>>>(x, 2);
    div_kernel<<<(N_GRAPHS * D + 255) / 256, 256>>>();
    fc1_kernel<<<N_GRAPHS, 256>>>(fcw, fcb);
    fc2_kernel<<<(N_GRAPHS * DOUT + 127) / 128, 128>>>(regw, regb, out);
}

// dedicated zero kernels over device globals
__global__ void zero_agg_kernel() {
    int i = blockIdx.x * blockDim.x + threadIdx.x;
    if (i < N_NODES * D / 4)
        reinterpret_cast<float4*>(g_agg)[i] = make_float4(0.f, 0.f, 0.f, 0.f);
}
__global__ void zero_pool_kernel() {
    int i = blockIdx.x * blockDim.x + threadIdx.x;
    int n4 = N_GRAPHS * D / 4;
    if (i < n4)
        reinterpret_cast<float4*>(g_pool)[i] = make_float4(0.f, 0.f, 0.f, 0.f);
    else if (i < n4 + N_GRAPHS / 4)
        reinterpret_cast<float4*>(g_cnt)[i - n4] = make_float4(0.f, 0.f, 0.f, 0.f);
}

// round 2
// speedup vs baseline: 1.5118x; 1.5118x over previous
#include <cuda_runtime.h>
#include <cstdint>

#define N_NODES 100000
#define N_EDGES 1600000
#define N_GRAPHS 2048
#define D 128
#define DFC 256
#define DOUT 8

#define SCAN_CHUNK 1024
#define SCAN_NB ((N_NODES + SCAN_CHUNK - 1) / SCAN_CHUNK)   // 98

// ---------------- scratch (static device globals; no allocation) ----------------
__device__ float g_agg[(size_t)N_NODES * D];
__device__ float g_hA[(size_t)N_NODES * D];
__device__ float g_hB[(size_t)N_NODES * D];
__device__ float g_pool[(size_t)N_GRAPHS * D];
__device__ float g_fc1[(size_t)N_GRAPHS * DFC];
__device__ int   g_src[N_EDGES];
__device__ int   g_dst[N_EDGES];
__device__ int   g_batch[N_NODES];
__device__ int   g_counts[N_NODES];          // zeroed by cudaMemsetAsync
__device__ int   g_row_ptr[N_NODES + 1];
__device__ int   g_cursor[N_NODES];
__device__ int   g_csr_src[N_EDGES];
__device__ int   g_blocksum[SCAN_NB];

// selector: 0 -> external x, 1 -> g_hA, 2 -> g_hB
__device__ __forceinline__ const float* pick_in(const float* x, int sel) {
    return sel == 0 ? x : (sel == 1 ? g_hA : g_hB);
}
__device__ __forceinline__ float* pick_out(int sel) {
    return sel == 1 ? g_hA : g_hB;
}

// ---------------- convert indices (self-detecting dtype) + per-dst counts ----------------
__device__ __forceinline__ int detect_is64(const void* ei) {
    const long long* p64 = (const long long*)ei;
    int ok = 1;
    #pragma unroll
    for (int i = 0; i < 16; i++) {
        long long v = __ldg(&p64[i]);
        if (v < 0 || v >= N_NODES) ok = 0;
    }
    return ok;
}

__global__ void convert_count_kernel(const void* ei, const void* batch) {
    int i = blockIdx.x * blockDim.x + threadIdx.x;
    int is64 = detect_is64(ei);   // broadcast loads, L1-resident; per-thread redundant but cheap
    if (i < N_EDGES) {
        int s, d;
        if (is64) {
            const long long* p = (const long long*)ei;
            s = (int)__ldg(&p[i]);
            d = (int)__ldg(&p[(size_t)N_EDGES + i]);
        } else {
            const int* p = (const int*)ei;
            s = __ldg(&p[i]);
            d = __ldg(&p[N_EDGES + i]);
        }
        g_src[i] = s;
        g_dst[i] = d;
        atomicAdd(&g_counts[d], 1);
    }
    if (i < N_NODES) {
        if (is64) g_batch[i] = (int)__ldg(&((const long long*)batch)[i]);
        else      g_batch[i] = __ldg(&((const int*)batch)[i]);
    }
}

// ---------------- scan: counts -> row_ptr (exclusive) ----------------
__global__ void scan1_kernel() {           // per-chunk totals
    __shared__ int sh[256];
    int b = blockIdx.x, t = threadIdx.x;
    int i0 = b * SCAN_CHUNK + t * 4;
    int s = 0;
    #pragma unroll
    for (int j = 0; j < 4; j++) {
        int i = i0 + j;
        if (i < N_NODES) s += g_counts[i];
    }
    sh[t] = s;
    __syncthreads();
    for (int off = 128; off > 0; off >>= 1) {
        if (t < off) sh[t] += sh[t + off];
        __syncthreads();
    }
    if (t == 0) g_blocksum[b] = sh[0];
}

__global__ void scan2_kernel() {           // scan chunk totals (tiny, single thread)
    if (threadIdx.x == 0 && blockIdx.x == 0) {
        int run = 0;
        for (int b = 0; b < SCAN_NB; b++) {
            int v = g_blocksum[b];
            g_blocksum[b] = run;
            run += v;
        }
        g_row_ptr[N_NODES] = run;          // == N_EDGES
    }
}

__global__ void scan3_kernel() {           // final exclusive scan + cursor init
    __shared__ int sh[256];
    int b = blockIdx.x, t = threadIdx.x;
    int i0 = b * SCAN_CHUNK + t * 4;
    int c[4];
    int tsum = 0;
    #pragma unroll
    for (int j = 0; j < 4; j++) {
        int i = i0 + j;
        c[j] = (i < N_NODES) ? g_counts[i] : 0;
        tsum += c[j];
    }
    sh[t] = tsum;
    __syncthreads();
    // Hillis-Steele inclusive scan over 256 thread sums
    #pragma unroll
    for (int off = 1; off < 256; off <<= 1) {
        int v = (t >= off) ? sh[t - off] : 0;
        __syncthreads();
        sh[t] += v;
        __syncthreads();
    }
    int base = g_blocksum[b] + sh[t] - tsum;   // exclusive prefix for this thread
    #pragma unroll
    for (int j = 0; j < 4; j++) {
        int i = i0 + j;
        if (i < N_NODES) {
            g_row_ptr[i] = base;
            g_cursor[i]  = base;
            base += c[j];
        }
    }
}

// ---------------- fill CSR ----------------
__global__ void fill_kernel() {
    int e = blockIdx.x * blockDim.x + threadIdx.x;
    if (e >= N_EDGES) return;
    int d = g_dst[e];
    int pos = atomicAdd(&g_cursor[d], 1);
    g_csr_src[pos] = g_src[e];
}

// ---------------- gather: agg[n] = sum over csr edges of h[src] (no atomics) ----------------
__global__ void gather_kernel(const float* __restrict__ x, int sel_in) {
    long long idx = (long long)blockIdx.x * blockDim.x + threadIdx.x;
    int node = (int)(idx >> 5);
    if (node >= N_NODES) return;
    int lane = (int)(idx & 31);
    const float* h = pick_in(x, sel_in);
    const float4* h4 = reinterpret_cast<const float4*>(h);
    int beg = g_row_ptr[node];
    int end = g_row_ptr[node + 1];
    float4 acc = make_float4(0.f, 0.f, 0.f, 0.f);
    int e = beg;
    for (; e + 4 <= end; e += 4) {
        int s0 = __ldg(&g_csr_src[e]);
        int s1 = __ldg(&g_csr_src[e + 1]);
        int s2 = __ldg(&g_csr_src[e + 2]);
        int s3 = __ldg(&g_csr_src[e + 3]);
        float4 v0 = __ldg(&h4[(size_t)s0 * 32 + lane]);
        float4 v1 = __ldg(&h4[(size_t)s1 * 32 + lane]);
        float4 v2 = __ldg(&h4[(size_t)s2 * 32 + lane]);
        float4 v3 = __ldg(&h4[(size_t)s3 * 32 + lane]);
        acc.x += v0.x; acc.y += v0.y; acc.z += v0.z; acc.w += v0.w;
        acc.x += v1.x; acc.y += v1.y; acc.z += v1.z; acc.w += v1.w;
        acc.x += v2.x; acc.y += v2.y; acc.z += v2.z; acc.w += v2.w;
        acc.x += v3.x; acc.y += v3.y; acc.z += v3.z; acc.w += v3.w;
    }
    for (; e < end; e++) {
        int s = __ldg(&g_csr_src[e]);
        float4 v = __ldg(&h4[(size_t)s * 32 + lane]);
        acc.x += v.x; acc.y += v.y; acc.z += v.z; acc.w += v.w;
    }
    reinterpret_cast<float4*>(g_agg)[(size_t)node * 32 + lane] = acc;
}

// ---------------- fused dual-GEMM + bias + relu ----------------
// out = relu(agg @ Wrel + hin @ Wroot + b)
__global__ __launch_bounds__(256) void gemm_fused_kernel(
    const float* __restrict__ x, int sel_in, int sel_out,
    const float* __restrict__ Wrel, const float* __restrict__ Wroot,
    const float* __restrict__ bias)
{
    __shared__ float As[128][16];
    __shared__ float Bs[16][128];

    const float* hin = pick_in(x, sel_in);
    float* hout = pick_out(sel_out);

    int m0 = blockIdx.x * 128;
    int tid = threadIdx.x;
    int tx = tid & 15;
    int ty = tid >> 4;

    unsigned long long acc[8][4];
    #pragma unroll
    for (int r = 0; r < 8; r++)
        #pragma unroll
        for (int j = 0; j < 4; j++) acc[r][j] = 0ULL;

    #pragma unroll
    for (int phase = 0; phase < 2; phase++) {
        const float* A = phase ? hin : g_agg;
        const float* W = phase ? Wroot : Wrel;
        for (int k0 = 0; k0 < 128; k0 += 16) {
            #pragma unroll
            for (int i = 0; i < 2; i++) {
                int f = tid * 2 + i;
                int row = f >> 2;
                int c4 = f & 3;
                int gr = m0 + row;
                float4 v = make_float4(0.f, 0.f, 0.f, 0.f);
                if (gr < N_NODES)
                    v = *reinterpret_cast<const float4*>(A + (size_t)gr * 128 + k0 + c4 * 4);
                *reinterpret_cast<float4*>(&As[row][c4 * 4]) = v;
            }
            #pragma unroll
            for (int i = 0; i < 2; i++) {
                int f = tid * 2 + i;
                int kr = f >> 5;
                int c4 = f & 31;
                float4 v = *reinterpret_cast<const float4*>(W + (size_t)(k0 + kr) * 128 + c4 * 4);
                *reinterpret_cast<float4*>(&Bs[kr][c4 * 4]) = v;
            }
            __syncthreads();

            #pragma unroll
            for (int k = 0; k < 16; k += 4) {
                float4 av[8];
                #pragma unroll
                for (int r = 0; r < 8; r++)
                    av[r] = *reinterpret_cast<const float4*>(&As[ty * 8 + r][k]);
                #pragma unroll
                for (int kk = 0; kk < 4; kk++) {
                    unsigned long long bb[4];
                    const unsigned long long* Brow =
                        reinterpret_cast<const unsigned long long*>(&Bs[k + kk][0]);
                    #pragma unroll
                    for (int j = 0; j < 4; j++) bb[j] = Brow[tx + 16 * j];
                    #pragma unroll
                    for (int r = 0; r < 8; r++) {
                        float a = (kk == 0) ? av[r].x : (kk == 1) ? av[r].y
                                : (kk == 2) ? av[r].z : av[r].w;
                        unsigned long long aa;
                        asm("mov.b64 %0,{%1,%2};" : "=l"(aa) : "f"(a), "f"(a));
                        #pragma unroll
                        for (int j = 0; j < 4; j++)
                            asm("fma.rn.f32x2 %0, %1, %2, %0;"
                                : "+l"(acc[r][j]) : "l"(aa), "l"(bb[j]));
                    }
                }
            }
            __syncthreads();
        }
    }

    #pragma unroll
    for (int r = 0; r < 8; r++) {
        int gr = m0 + ty * 8 + r;
        if (gr >= N_NODES) break;
        #pragma unroll
        for (int j = 0; j < 4; j++) {
            int p = tx + 16 * j;
            float2 v = *reinterpret_cast<float2*>(&acc[r][j]);
            float lo = fmaxf(v.x + bias[2 * p], 0.f);
            float hi = fmaxf(v.y + bias[2 * p + 1], 0.f);
            *reinterpret_cast<float2*>(&hout[(size_t)gr * 128 + 2 * p]) = make_float2(lo, hi);
        }
    }
}

// ---------------- pool: sorted-batch segments, block per graph, no atomics ----------------
__device__ __forceinline__ int lower_bound_batch(int v) {
    int lo = 0, hi = N_NODES;
    while (lo < hi) {
        int m = (lo + hi) >> 1;
        if (g_batch[m] < v) lo = m + 1; else hi = m;
    }
    return lo;
}

__global__ __launch_bounds__(128) void pool_kernel(const float* __restrict__ x, int sel_in) {
    int g = blockIdx.x;
    int t = threadIdx.x;           // dim 0..127
    const float* h = pick_in(x, sel_in);
    int lo = lower_bound_batch(g);
    int hi = lower_bound_batch(g + 1);
    float acc = 0.f;
    for (int n = lo; n < hi; n++)
        acc += __ldg(&h[(size_t)n * 128 + t]);
    float cnt = (float)(hi - lo);
    g_pool[(size_t)g * 128 + t] = acc / fmaxf(cnt, 1.0f);
}

// ---------------- fc1: 4 graphs per block, [G,128]@[128,256]+b ----------------
__global__ __launch_bounds__(256) void fc1_kernel(
    const float* __restrict__ w, const float* __restrict__ b)
{
    __shared__ float p[4][128];
    int g0 = blockIdx.x * 4;
    int t = threadIdx.x;
    #pragma unroll
    for (int i = 0; i < 2; i++) {
        int f = t + i * 256;      // 0..511
        p[f >> 7][f & 127] = g_pool[(size_t)g0 * 128 + f];
    }
    __syncthreads();
    float acc0 = b[t], acc1 = b[t], acc2 = b[t], acc3 = b[t];
    #pragma unroll 4
    for (int k = 0; k < 128; k++) {
        float wv = __ldg(&w[(size_t)k * 256 + t]);
        acc0 = fmaf(p[0][k], wv, acc0);
        acc1 = fmaf(p[1][k], wv, acc1);
        acc2 = fmaf(p[2][k], wv, acc2);
        acc3 = fmaf(p[3][k], wv, acc3);
    }
    g_fc1[(size_t)(g0 + 0) * 256 + t] = acc0;
    g_fc1[(size_t)(g0 + 1) * 256 + t] = acc1;
    g_fc1[(size_t)(g0 + 2) * 256 + t] = acc2;
    g_fc1[(size_t)(g0 + 3) * 256 + t] = acc3;
}

// ---------------- fc2: [G,256]@[256,8]+b -> out ----------------
__global__ void fc2_kernel(const float* __restrict__ w, const float* __restrict__ b,
                           float* __restrict__ out)
{
    int idx = blockIdx.x * blockDim.x + threadIdx.x;
    if (idx >= N_GRAPHS * DOUT) return;
    int g = idx >> 3, o = idx & 7;
    float acc = b[o];
    #pragma unroll 8
    for (int k = 0; k < 256; k++)
        acc = fmaf(g_fc1[(size_t)g * 256 + k], __ldg(&w[k * 8 + o]), acc);
    out[idx] = acc;
}

// ---------------- launch ----------------
extern "C" void kernel_launch(void* const* d_in, const int* in_sizes, int n_in,
                              void* d_out, int out_size)
{
    const float* x = (const float*)d_in[0];
    const void* ei = d_in[1];
    const void* batch = d_in[2];
    const float* Wrel[4]  = {(const float*)d_in[3], (const float*)d_in[6],
                             (const float*)d_in[9], (const float*)d_in[12]};
    const float* Wroot[4] = {(const float*)d_in[4], (const float*)d_in[7],
                             (const float*)d_in[10], (const float*)d_in[13]};
    const float* bias[4]  = {(const float*)d_in[5], (const float*)d_in[8],
                             (const float*)d_in[11], (const float*)d_in[14]};
    const float* fcw = (const float*)d_in[15];
    const float* fcb = (const float*)d_in[16];
    const float* regw = (const float*)d_in[17];
    const float* regb = (const float*)d_in[18];
    float* out = (float*)d_out;

    // zero the per-dst counts via memset node (not a kernel launch)
    void* countsPtr = nullptr;
    cudaGetSymbolAddress(&countsPtr, g_counts);
    cudaMemsetAsync(countsPtr, 0, N_NODES * sizeof(int));

    // CSR build
    convert_count_kernel<<<(N_EDGES + 255) / 256, 256>>>(ei, batch);      // k0
    scan1_kernel<<<SCAN_NB, 256>>>();                                     // k1
    scan2_kernel<<<1, 32>>>();                                            // k2
    scan3_kernel<<<SCAN_NB, 256>>>();                                     // k3
    fill_kernel<<<(N_EDGES + 255) / 256, 256>>>();                        // k4

    const int gatherBlocks = (int)(((long long)N_NODES * 32 + 255) / 256);
    const int gemmBlocks = (N_NODES + 127) / 128;

    int ins[4]  = {0, 1, 2, 1};
    int outs[4] = {1, 2, 1, 2};
    for (int L = 0; L < 4; L++) {
        gather_kernel<<<gatherBlocks, 256>>>(x, ins[L]);                  // k5 = first gather
        gemm_fused_kernel<<<gemmBlocks, 256>>>(x, ins[L], outs[L],
                                               Wrel[L], Wroot[L], bias[L]);
    }

    pool_kernel<<<N_GRAPHS, 128>>>(x, 2);
    fc1_kernel<<<N_GRAPHS / 4, 256>>>(fcw, fcb);
    fc2_kernel<<<(N_GRAPHS * DOUT + 127) / 128, 128>>>(regw, regb, out);
}